// round 1
// baseline (speedup 1.0000x reference)
#include <cuda_runtime.h>

#define Bn   16
#define Tn   262144
#define HOP  256
#define WINL 1024
#define PADL 384
#define Fn   1024          // Tn / HOP
#define Pn   22
#define EXPLEN (Tn + 2*PADL)   // 262912

// Scratch (device globals: no allocation allowed in kernel_launch)
__device__ float d_expbuf[Bn * EXPLEN];   // padded excitation
__device__ float d_acc[Bn * EXPLEN];      // OLA accumulator (padded domain)
__device__ float d_w[WINL];               // periodic Hann window

// ---------------------------------------------------------------------------
// Kernel 1: build padded excitation, zero the OLA accumulator, build window
// ---------------------------------------------------------------------------
__global__ void prep_kernel(const float* __restrict__ ex) {
    int i = blockIdx.x * blockDim.x + threadIdx.x;
    if (i < WINL) {
        d_w[i] = 0.5f * (1.0f - cosf(6.283185307179586f * (float)i / (float)WINL));
    }
    if (i < Bn * EXPLEN) {
        int b = i / EXPLEN;
        int n = i - b * EXPLEN;
        float v = 0.0f;
        if (n >= PADL && n < PADL + Tn) v = ex[b * Tn + (n - PADL)];
        d_expbuf[i] = v;
        d_acc[i] = 0.0f;
    }
}

// ---------------------------------------------------------------------------
// Kernel 2: per-sequence LPC synthesis (transposed DF-II) + window + OLA
//   One thread per (b,f) sequence. Warp = 32 consecutive frames of one batch.
//   Every 32 steps: smem 32x32 transpose -> coalesced atomicAdd into d_acc.
// ---------------------------------------------------------------------------
__global__ void __launch_bounds__(128, 1)
lpc_kernel(const float* __restrict__ gain, const float* __restrict__ a) {
    __shared__ float tile[4][32][33];

    const int warp = threadIdx.x >> 5;
    const int lane = threadIdx.x & 31;
    const int gw   = blockIdx.x * 4 + warp;   // global warp id, 0..511
    const int s0   = gw * 32;                 // warp-base sequence index
    const int s    = s0 + lane;               // this thread's sequence (b*Fn+f)
    const int b    = s >> 10;                 // Fn = 1024
    const int f    = s & (Fn - 1);
    const int f0   = s0 & (Fn - 1);           // warp-base frame (same b for whole warp)

    const float g = gain[s];
    float na[Pn];
    #pragma unroll
    for (int p = 0; p < Pn; ++p) na[p] = -a[s * Pn + p];

    float st[Pn];
    #pragma unroll
    for (int p = 0; p < Pn; ++p) st[p] = 0.0f;

    const float* __restrict__ xp   = d_expbuf + b * EXPLEN + f * HOP;
    float* __restrict__       accb = d_acc    + b * EXPLEN;

    for (int c = 0; c < 32; ++c) {
        const int t0 = c * 32;
        const float wv = d_w[t0 + lane];   // window value for this lane's write time

        #pragma unroll
        for (int ss = 0; ss < 32; ++ss) {
            const float x = xp[t0 + ss];
            const float y = fmaf(g, x, st[0]);
            #pragma unroll
            for (int p = 0; p < Pn - 1; ++p)
                st[p] = fmaf(na[p], y, st[p + 1]);
            st[Pn - 1] = na[Pn - 1] * y;
            tile[warp][ss][lane] = y;
        }
        __syncwarp();

        // transpose: lane l handles time t0+l for frame f0+r -> coalesced RED
        #pragma unroll
        for (int r = 0; r < 32; ++r) {
            const float val = tile[warp][lane][r] * wv;
            atomicAdd(&accb[(f0 + r) * HOP + t0 + lane], val);
        }
        __syncwarp();
    }
}

// ---------------------------------------------------------------------------
// Kernel 3: crop + divide by OLA-of-window norm (reconstructed analytically
// from the window table: <=4 frames contribute per sample; 2.0 in interior)
// ---------------------------------------------------------------------------
__global__ void final_kernel(float* __restrict__ out) {
    int i = blockIdx.x * blockDim.x + threadIdx.x;
    if (i >= Bn * Tn) return;
    const int b = i >> 18;                 // Tn = 2^18
    const int n = i & (Tn - 1);
    const int pos = n + PADL;

    const float num = d_acc[b * EXPLEN + pos];

    float norm = 0.0f;
    const int fhi = pos >> 8;              // HOP = 256
    #pragma unroll
    for (int k = 0; k < 4; ++k) {
        const int ff = fhi - k;
        const int t  = pos - ff * HOP;     // in [0, 1024) whenever ff valid
        if (ff >= 0 && ff < Fn) norm += d_w[t];
    }
    out[i] = num / norm;
}

// ---------------------------------------------------------------------------
extern "C" void kernel_launch(void* const* d_in, const int* in_sizes, int n_in,
                              void* d_out, int out_size) {
    const float* ex   = (const float*)d_in[0];
    const float* gain = (const float*)d_in[1];
    const float* a    = (const float*)d_in[2];
    float* out = (float*)d_out;

    const int totalPrep = Bn * EXPLEN;
    prep_kernel<<<(totalPrep + 255) / 256, 256>>>(ex);
    lpc_kernel<<<128, 128>>>(gain, a);
    final_kernel<<<(Bn * Tn + 255) / 256, 256>>>(out);
}

// round 2
// speedup vs baseline: 2.8845x; 2.8845x over previous
#include <cuda_runtime.h>

#define Bn   16
#define Tn   262144
#define HOP  256
#define WINL 1024
#define PADL 384
#define Fn   1024          // Tn / HOP
#define Pn   22
#define NSEQ (Bn * Fn)     // 16384 independent filters

// Scratch device globals (no allocation allowed in kernel_launch)
__device__ float d_frames[(size_t)NSEQ * WINL];  // 64MB: windowed synthesized frames
__device__ float d_w[WINL];                      // periodic Hann window

// ---------------------------------------------------------------------------
// Kernel 0: window table (tiny)
// ---------------------------------------------------------------------------
__global__ void win_kernel() {
    int i = threadIdx.x;
    d_w[i] = 0.5f * (1.0f - cosf(6.283185307179586f * (float)i / (float)WINL));
}

// ---------------------------------------------------------------------------
// Kernel 1: per-sequence LPC synthesis (transposed DF-II), window, write frames
//   One thread per (b,f) sequence; warp = 32 consecutive frames of one batch.
//   Input staged per 32-step chunk via coalesced loads (register double-buffer)
//   Output transposed in smem -> fully coalesced STG (no atomics).
// ---------------------------------------------------------------------------
__global__ void __launch_bounds__(128, 1)
lpc_kernel(const float* __restrict__ ex,
           const float* __restrict__ gain,
           const float* __restrict__ a) {
    __shared__ float xs  [4][32][33];  // staged excitation  [row=frame][col=time]
    __shared__ float tile[4][32][33];  // output transpose   [row=time ][col=frame]

    const int warp = threadIdx.x >> 5;
    const int lane = threadIdx.x & 31;
    const int gw   = blockIdx.x * 4 + warp;   // 0..511
    const int s0   = gw * 32;                 // warp-base sequence index
    const int s    = s0 + lane;
    const int b    = s >> 10;                 // Fn = 1024
    const int f0   = s0 & (Fn - 1);           // warp-base frame (same b whole warp)

    const float g = gain[s];
    float na[Pn], st[Pn];
    #pragma unroll
    for (int p = 0; p < Pn; ++p) { na[p] = -a[s * Pn + p]; st[p] = 0.0f; }

    const float* __restrict__ exb = ex + b * Tn;

    // prefetch chunk 0 (coalesced: lane sweeps time, r sweeps frames)
    float xr[32];
    #pragma unroll
    for (int r = 0; r < 32; ++r) {
        int idx = (f0 + r) * HOP + lane - PADL;
        xr[r] = ((unsigned)idx < (unsigned)Tn) ? exb[idx] : 0.0f;
    }

    for (int c = 0; c < 32; ++c) {
        const int t0 = c * 32;

        // commit prefetched chunk to smem
        #pragma unroll
        for (int r = 0; r < 32; ++r) xs[warp][r][lane] = xr[r];
        __syncwarp();

        // issue next chunk's loads now; latency hides under the recurrence
        if (c < 31) {
            const int t1 = t0 + 32;
            #pragma unroll
            for (int r = 0; r < 32; ++r) {
                int idx = (f0 + r) * HOP + t1 + lane - PADL;
                xr[r] = ((unsigned)idx < (unsigned)Tn) ? exb[idx] : 0.0f;
            }
        }

        // 32 recurrence steps (transposed direct-form II: 23 FMA/step, no shifts)
        #pragma unroll
        for (int ss = 0; ss < 32; ++ss) {
            const float x = xs[warp][lane][ss];
            const float y = fmaf(g, x, st[0]);
            #pragma unroll
            for (int p = 0; p < Pn - 1; ++p)
                st[p] = fmaf(na[p], y, st[p + 1]);
            st[Pn - 1] = na[Pn - 1] * y;
            tile[warp][ss][lane] = y;
        }
        __syncwarp();

        // transpose + window + coalesced frame write
        const float wv = d_w[t0 + lane];
        float* __restrict__ fout = d_frames + (size_t)s0 * WINL + t0 + lane;
        #pragma unroll
        for (int r = 0; r < 32; ++r)
            fout[(size_t)r * WINL] = tile[warp][lane][r] * wv;
        __syncwarp();
    }
}

// ---------------------------------------------------------------------------
// Kernel 2: gather-OLA. Each output sample = sum of exactly <=4 frame samples.
//   Interior norm is exactly 2.0 (4-phase periodic Hann identity); edges use
//   the window table. float4 everywhere (pos group never crosses a frame edge
//   since 4 | HOP).
// ---------------------------------------------------------------------------
__global__ void final_kernel(float* __restrict__ out) {
    const int i = blockIdx.x * blockDim.x + threadIdx.x;   // float4 group id
    if (i >= Bn * Tn / 4) return;
    const int b   = i >> 16;                // Tn/4 = 65536 groups per batch
    const int n0  = (i & 65535) << 2;
    const int pos = n0 + PADL;
    const int fhi = pos >> 8;               // HOP = 256; constant across group

    const float* __restrict__ fb = d_frames + (size_t)b * Fn * WINL;
    float4 acc = make_float4(0.f, 0.f, 0.f, 0.f);
    #pragma unroll
    for (int k = 0; k < 4; ++k) {
        const int ff = fhi - k;
        if (ff >= 0 && ff < Fn) {
            const float4 v = *(const float4*)(fb + (size_t)ff * WINL + (pos - ff * HOP));
            acc.x += v.x; acc.y += v.y; acc.z += v.z; acc.w += v.w;
        }
    }

    float4 o;
    if (pos >= 3 * HOP && fhi <= Fn - 1) {           // interior: norm == 2
        o.x = acc.x * 0.5f; o.y = acc.y * 0.5f;
        o.z = acc.z * 0.5f; o.w = acc.w * 0.5f;
    } else {                                         // 2x384 samples per batch
        float nrm[4] = {0.f, 0.f, 0.f, 0.f};
        #pragma unroll
        for (int j = 0; j < 4; ++j) {
            #pragma unroll
            for (int k = 0; k < 4; ++k) {
                const int ff = fhi - k;
                if (ff >= 0 && ff < Fn) nrm[j] += d_w[pos + j - ff * HOP];
            }
        }
        o.x = acc.x / nrm[0]; o.y = acc.y / nrm[1];
        o.z = acc.z / nrm[2]; o.w = acc.w / nrm[3];
    }
    ((float4*)out)[i] = o;
}

// ---------------------------------------------------------------------------
extern "C" void kernel_launch(void* const* d_in, const int* in_sizes, int n_in,
                              void* d_out, int out_size) {
    const float* ex   = (const float*)d_in[0];
    const float* gain = (const float*)d_in[1];
    const float* a    = (const float*)d_in[2];
    float* out = (float*)d_out;

    win_kernel<<<1, WINL>>>();
    lpc_kernel<<<128, 128>>>(ex, gain, a);
    final_kernel<<<(Bn * Tn / 4 + 255) / 256, 256>>>(out);
}

// round 3
// speedup vs baseline: 3.1810x; 1.1028x over previous
#include <cuda_runtime.h>

#define Bn   16
#define Tn   262144
#define HOP  256
#define WINL 1024
#define PADL 384
#define Fn   1024          // Tn / HOP
#define Pn   22
#define NSEQ (Bn * Fn)     // 16384 independent filters

// Scratch device global (no allocation allowed in kernel_launch)
__device__ float d_frames[(size_t)NSEQ * WINL];  // 64MB: windowed synthesized frames

typedef unsigned long long ull;

static __device__ __forceinline__ ull pk2(float lo, float hi) {
    ull r; asm("mov.b64 %0,{%1,%2};" : "=l"(r) : "f"(lo), "f"(hi)); return r;
}
static __device__ __forceinline__ void upk2(float& lo, float& hi, ull v) {
    asm("mov.b64 {%0,%1},%2;" : "=f"(lo), "=f"(hi) : "l"(v));
}
static __device__ __forceinline__ ull fma2_(ull a, ull b, ull c) {
    ull r; asm("fma.rn.f32x2 %0,%1,%2,%3;" : "=l"(r) : "l"(a), "l"(b), "l"(c)); return r;
}
static __device__ __forceinline__ ull mul2_(ull a, ull b) {
    ull r; asm("mul.rn.f32x2 %0,%1,%2;" : "=l"(r) : "l"(a), "l"(b)); return r;
}

static __device__ __forceinline__ float hannf(int t) {
    return 0.5f - 0.5f * cosf(6.283185307179586f * (float)t * (1.0f / 1024.0f));
}

// ---------------------------------------------------------------------------
// Kernel 1: per-sequence LPC synthesis, 2-step blocked + packed f32x2 FMAs.
//   One thread per (b,f) sequence; warp = 32 consecutive frames of one batch.
//   Input staged per 32-step chunk via coalesced loads (register double-buffer)
//   Output transposed in smem -> fully coalesced windowed frame STG.
// ---------------------------------------------------------------------------
__global__ void __launch_bounds__(128, 1)
lpc_kernel(const float* __restrict__ ex,
           const float* __restrict__ gain,
           const float* __restrict__ a) {
    __shared__ float xs  [4][32][33];  // staged excitation  [row=frame][col=time]
    __shared__ float tile[4][32][33];  // output transpose   [row=time ][col=frame]

    const int warp = threadIdx.x >> 5;
    const int lane = threadIdx.x & 31;
    const int gw   = blockIdx.x * 4 + warp;   // 0..511
    const int s0   = gw * 32;                 // warp-base sequence index
    const int s    = s0 + lane;
    const int b    = s >> 10;                 // Fn = 1024
    const int f0   = s0 & (Fn - 1);           // warp-base frame (same b whole warp)

    const float g = gain[s];

    // c[q] = -a[q-1] (q=1..22), c[23] = 0 ; d[q] = c1*c[q] + c[q+1]
    float c[24];
    #pragma unroll
    for (int p = 0; p < Pn; ++p) c[p + 1] = -a[s * Pn + p];
    c[23] = 0.0f;
    const float c1  = c[1];
    const float c1g = c1 * g;

    ull CA[11], CB[11], H[11];
    #pragma unroll
    for (int k = 0; k < 11; ++k) {
        const float dlo = fmaf(c1, c[2 * k + 1], c[2 * k + 2]);
        const float dhi = fmaf(c1, c[2 * k + 2], c[2 * k + 3]);
        CA[k] = pk2(c[2 * k + 1], c[2 * k + 2]);
        CB[k] = pk2(dlo, dhi);
        H[k]  = 0ull;   // zero initial state
    }

    const float* __restrict__ exb = ex + b * Tn;

    // prefetch chunk 0 (coalesced: lane sweeps time, r sweeps frames)
    float xr[32];
    #pragma unroll
    for (int r = 0; r < 32; ++r) {
        int idx = (f0 + r) * HOP + lane - PADL;
        xr[r] = ((unsigned)idx < (unsigned)Tn) ? exb[idx] : 0.0f;
    }

    for (int cchunk = 0; cchunk < 32; ++cchunk) {
        const int t0 = cchunk * 32;

        // commit prefetched chunk to smem
        #pragma unroll
        for (int r = 0; r < 32; ++r) xs[warp][r][lane] = xr[r];
        __syncwarp();

        // issue next chunk's loads now; latency hides under the recurrence
        if (cchunk < 31) {
            const int t1 = t0 + 32;
            #pragma unroll
            for (int r = 0; r < 32; ++r) {
                int idx = (f0 + r) * HOP + t1 + lane - PADL;
                xr[r] = ((unsigned)idx < (unsigned)Tn) ? exb[idx] : 0.0f;
            }
        }

        // 16 blocks x 2 samples: dot products vs shared history (packed pairs)
        #pragma unroll
        for (int bk = 0; bk < 16; ++bk) {
            const float x0 = xs[warp][lane][2 * bk];
            const float x1 = xs[warp][lane][2 * bk + 1];

            ull accA = mul2_(CA[0], H[0]);
            ull accB = mul2_(CB[0], H[0]);
            #pragma unroll
            for (int k = 1; k < 11; ++k) {
                accA = fma2_(CA[k], H[k], accA);
                accB = fma2_(CB[k], H[k], accB);
            }
            float aLo, aHi, bLo, bHi;
            upk2(aLo, aHi, accA);
            upk2(bLo, bHi, accB);

            const float y0 = fmaf(g, x0, aLo + aHi);
            const float y1 = fmaf(g, x1, fmaf(c1g, x0, bLo + bHi));

            tile[warp][2 * bk][lane]     = y0;
            tile[warp][2 * bk + 1][lane] = y1;

            // shift history by one pair; new pair = (y_{t+1}, y_t)
            #pragma unroll
            for (int k = 10; k > 0; --k) H[k] = H[k - 1];
            H[0] = pk2(y1, y0);
        }
        __syncwarp();

        // transpose + window + coalesced frame write
        const float wv = hannf(t0 + lane);
        float* __restrict__ fout = d_frames + (size_t)s0 * WINL + t0 + lane;
        #pragma unroll
        for (int r = 0; r < 32; ++r)
            fout[(size_t)r * WINL] = tile[warp][lane][r] * wv;
        __syncwarp();
    }
}

// ---------------------------------------------------------------------------
// Kernel 2: gather-OLA. Each output sample = sum of exactly <=4 frame samples.
//   Interior norm is exactly 2.0 (4-phase periodic Hann identity); edges use
//   inline hann. float4 everywhere (group never crosses frame edge: 4 | HOP).
// ---------------------------------------------------------------------------
__global__ void final_kernel(float* __restrict__ out) {
    const int i = blockIdx.x * blockDim.x + threadIdx.x;   // float4 group id
    if (i >= Bn * Tn / 4) return;
    const int b   = i >> 16;                // Tn/4 = 65536 groups per batch
    const int n0  = (i & 65535) << 2;
    const int pos = n0 + PADL;
    const int fhi = pos >> 8;               // HOP = 256; constant across group

    const float* __restrict__ fb = d_frames + (size_t)b * Fn * WINL;
    float4 acc = make_float4(0.f, 0.f, 0.f, 0.f);
    #pragma unroll
    for (int k = 0; k < 4; ++k) {
        const int ff = fhi - k;
        if (ff >= 0 && ff < Fn) {
            const float4 v = *(const float4*)(fb + (size_t)ff * WINL + (pos - ff * HOP));
            acc.x += v.x; acc.y += v.y; acc.z += v.z; acc.w += v.w;
        }
    }

    float4 o;
    if (pos >= 3 * HOP && fhi <= Fn - 1) {           // interior: norm == 2
        o.x = acc.x * 0.5f; o.y = acc.y * 0.5f;
        o.z = acc.z * 0.5f; o.w = acc.w * 0.5f;
    } else {                                         // 2x384 samples per batch
        float nrm[4] = {0.f, 0.f, 0.f, 0.f};
        #pragma unroll
        for (int j = 0; j < 4; ++j) {
            #pragma unroll
            for (int k = 0; k < 4; ++k) {
                const int ff = fhi - k;
                if (ff >= 0 && ff < Fn) nrm[j] += hannf(pos + j - ff * HOP);
            }
        }
        o.x = acc.x / nrm[0]; o.y = acc.y / nrm[1];
        o.z = acc.z / nrm[2]; o.w = acc.w / nrm[3];
    }
    ((float4*)out)[i] = o;
}

// ---------------------------------------------------------------------------
extern "C" void kernel_launch(void* const* d_in, const int* in_sizes, int n_in,
                              void* d_out, int out_size) {
    const float* ex   = (const float*)d_in[0];
    const float* gain = (const float*)d_in[1];
    const float* a    = (const float*)d_in[2];
    float* out = (float*)d_out;

    lpc_kernel<<<128, 128>>>(ex, gain, a);
    final_kernel<<<(Bn * Tn / 4 + 255) / 256, 256>>>(out);
}